// round 3
// baseline (speedup 1.0000x reference)
#include <cuda_runtime.h>

#define N_NODES 20000
#define N_EDGES 640000
#define EPB 4   // edges per warp iteration in k2

// ---------------- scratch (static device memory, no allocation) ----------------
__device__ float g_y0 [N_NODES * 32];        // y0[n][u]
__device__ float g_y1t[N_NODES * 3 * 32];    // y1t[n][m][u]
__device__ float g_y2t[N_NODES * 5 * 32];    // y2t[n][m][u]
__device__ float g_sc [3 * N_NODES * 32];    // sc[h][n][w]
__device__ float g_mid[N_NODES * 96];        // segment-summed messages

__device__ __forceinline__ float silu_f(float x) {
    return x / (1.0f + __expf(-x));
}

// packed f32x2 helpers
__device__ __forceinline__ unsigned long long fma2(unsigned long long a,
                                                   unsigned long long b,
                                                   unsigned long long c) {
    unsigned long long d;
    asm("fma.rn.f32x2 %0, %1, %2, %3;" : "=l"(d) : "l"(a), "l"(b), "l"(c));
    return d;
}
__device__ __forceinline__ float hsum2(unsigned long long a) {
    float lo, hi;
    asm("mov.b64 {%0, %1}, %2;" : "=f"(lo), "=f"(hi) : "l"(a));
    return lo + hi;
}
__device__ __forceinline__ unsigned long long pack2(float lo, float hi) {
    unsigned long long p;
    asm("mov.b64 %0, {%1, %2};" : "=l"(p) : "f"(lo), "f"(hi));
    return p;
}

// ---------------- Kernel 1 (fused): y0/y1/y2 pre-linear + sc + zero mid ----------------
__global__ void k1_kernel(const float* __restrict__ x,
                          const float* __restrict__ na,
                          const float* __restrict__ W1_0,
                          const float* __restrict__ W1_1,
                          const float* __restrict__ W1_2,
                          const float* __restrict__ scW)
{
    __shared__ __align__(16) float w0s[1024], w1s[1024], w2s[1024];
    __shared__ __align__(16) float scs[12288];  // 48KB
    int t = threadIdx.x;
    for (int i = t; i < 1024; i += blockDim.x) {
        w0s[i] = W1_0[i]; w1s[i] = W1_1[i]; w2s[i] = W1_2[i];
    }
    for (int i = t; i < 12288; i += blockDim.x) scs[i] = scW[i];
    __syncthreads();

    int lane = t & 31;
    int n = (int)((blockIdx.x * blockDim.x + t) >> 5);
    if (n >= N_NODES) return;

    const float* xr = x + (size_t)n * 288;
    float x0r = xr[lane];
    float x1r[3], x2r[5];
#pragma unroll
    for (int m = 0; m < 3; m++) x1r[m] = xr[32 + lane * 3 + m];
#pragma unroll
    for (int m = 0; m < 5; m++) x2r[m] = xr[128 + lane * 5 + m];

    float nar = (lane < 4) ? na[n * 4 + lane] : 0.f;
    float na0 = __shfl_sync(0xffffffffu, nar, 0);
    float na1 = __shfl_sync(0xffffffffu, nar, 1);
    float na2 = __shfl_sync(0xffffffffu, nar, 2);
    float na3 = __shfl_sync(0xffffffffu, nar, 3);

    float a0 = 0.f;
    float a1[3] = {0.f, 0.f, 0.f};
    float a2[5] = {0.f, 0.f, 0.f, 0.f, 0.f};
    float sc[3] = {0.f, 0.f, 0.f};

#pragma unroll
    for (int u = 0; u < 32; u++) {
        float xv0 = __shfl_sync(0xffffffffu, x0r, u);
        a0 = fmaf(xv0, w0s[u * 32 + lane], a0);
#pragma unroll
        for (int m = 0; m < 3; m++) {
            float xv = __shfl_sync(0xffffffffu, x1r[m], u);
            a1[m] = fmaf(xv, w1s[u * 32 + lane], a1[m]);
        }
#pragma unroll
        for (int m = 0; m < 5; m++) {
            float xv = __shfl_sync(0xffffffffu, x2r[m], u);
            a2[m] = fmaf(xv, w2s[u * 32 + lane], a2[m]);
        }
        float c0 = xv0 * na0, c1 = xv0 * na1, c2 = xv0 * na2, c3 = xv0 * na3;
#pragma unroll
        for (int h = 0; h < 3; h++) {
            const float* p = scs + ((h * 32 + u) * 4) * 32 + lane;
            sc[h] = fmaf(c0, p[0],  sc[h]);
            sc[h] = fmaf(c1, p[32], sc[h]);
            sc[h] = fmaf(c2, p[64], sc[h]);
            sc[h] = fmaf(c3, p[96], sc[h]);
        }
    }
    const float inv  = 0.17677669529663687f;  // 1/sqrt(32)
    const float invs = 0.08838834764831845f;  // 1/sqrt(128)
    g_y0[n * 32 + lane] = a0 * inv;
#pragma unroll
    for (int m = 0; m < 3; m++) g_y1t[(n * 3 + m) * 32 + lane] = a1[m] * inv;
#pragma unroll
    for (int m = 0; m < 5; m++) g_y2t[(n * 5 + m) * 32 + lane] = a2[m] * inv;
#pragma unroll
    for (int h = 0; h < 3; h++)
        g_sc[h * (N_NODES * 32) + n * 32 + lane] = sc[h] * invs;

    g_mid[n * 96 + lane]      = 0.f;
    g_mid[n * 96 + 32 + lane] = 0.f;
    g_mid[n * 96 + 64 + lane] = 0.f;
}

// ---------------- Kernel 2: fused edge MLP + gather + message + scatter ----------------
// warp processes EPB=4 edges/iter. lane = channel. Gathers prefetched before GEMM.
__global__ void __launch_bounds__(256, 2) k2_kernel(const float* __restrict__ ee,
                          const float* __restrict__ ea,
                          const int*   __restrict__ eidx,
                          const float* __restrict__ Wm0,
                          const float* __restrict__ Wm1)
{
    __shared__ __align__(16) float wm1t[96 * 68];       // [c][k], stride 68
    __shared__ __align__(16) float hbuf[8][EPB][64];    // per-warp h
    __shared__ __align__(16) float msgb[8][EPB][96];    // per-warp messages
    __shared__ __align__(16) float eeb [8][EPB * 8];    // staged edge_embed
    __shared__ __align__(16) float eab [8][EPB * 9];    // staged edge_attrs

    int t = threadIdx.x;
    for (int i = t; i < 64 * 96; i += blockDim.x) {
        int j = i / 96, c = i % 96;
        wm1t[c * 68 + j] = Wm1[i];
    }
    __syncthreads();

    int lane = t & 31;
    int wrp  = t >> 5;

    // Wm0 packed over k-pairs: wa2[j] = (Wm0[2j][lane], Wm0[2j+1][lane])
    unsigned long long wa2[4], wb2[4];
#pragma unroll
    for (int j = 0; j < 4; j++) {
        wa2[j] = pack2(Wm0[(2 * j) * 64 + lane],      Wm0[(2 * j + 1) * 64 + lane]);
        wb2[j] = pack2(Wm0[(2 * j) * 64 + 32 + lane], Wm0[(2 * j + 1) * 64 + 32 + lane]);
    }

    const float inv8 = 0.35355339059327373f;            // 1/sqrt(8)
    const float C0 = 0.125f * 0.17677669529663687f;     // invh*savg
    const float C1 = C0 * 0.5773502691896258f;          // *1/sqrt3
    const float C2 = C0 * 0.4472135954999579f;          // *1/sqrt5

    int warpid = blockIdx.x * 8 + wrp;
    int nwarp  = gridDim.x * 8;
    const int niter = N_EDGES / EPB;

    for (int it = warpid; it < niter; it += nwarp) {
        int ebase = it * EPB;

        // ---- stage ee (32 floats) + ea (36 floats) coalesced into smem ----
        if (lane < 16) {
            float2 v = *(const float2*)&ee[(size_t)ebase * 8 + lane * 2];
            *(float2*)&eeb[wrp][lane * 2] = v;
        } else if (lane < 34) { // lanes 16..31 handle 16 of 18 float2
            int j = lane - 16;
            float2 v = *(const float2*)&ea[(size_t)ebase * 9 + j * 2];
            *(float2*)&eab[wrp][j * 2] = v;
        }
        if (lane < 2) {
            float2 v = *(const float2*)&ea[(size_t)ebase * 9 + 32 + lane * 2];
            *(float2*)&eab[wrp][32 + lane * 2] = v;
        }

        int sidx[EPB], didx[EPB];
#pragma unroll
        for (int e = 0; e < EPB; e++) {
            sidx[e] = __ldg(&eidx[ebase + e]);
            didx[e] = __ldg(&eidx[N_EDGES + ebase + e]);
        }

        // ---- prefetch gathers: in flight across h-stage + GEMM ----
        float y0v[EPB], y1v[EPB][3], y2v[EPB][5];
#pragma unroll
        for (int e = 0; e < EPB; e++) {
            const float* b0 = g_y0  + (size_t)sidx[e] * 32      + lane;
            const float* b1 = g_y1t + (size_t)sidx[e] * 96      + lane;
            const float* b2 = g_y2t + (size_t)sidx[e] * 160     + lane;
            y0v[e] = __ldg(b0);
#pragma unroll
            for (int m = 0; m < 3; m++) y1v[e][m] = __ldg(b1 + m * 32);
#pragma unroll
            for (int m = 0; m < 5; m++) y2v[e][m] = __ldg(b2 + m * 32);
        }
        __syncwarp();

        // ---- h = silu(ee @ Wm0 / sqrt8), packed f32x2 over k ----
#pragma unroll
        for (int e = 0; e < EPB; e++) {
            const float* eep = &eeb[wrp][e * 8];
            unsigned long long ha2 = 0ull, hb2 = 0ull;
#pragma unroll
            for (int j = 0; j < 4; j++) {
                unsigned long long e2 = *(const unsigned long long*)(eep + 2 * j);
                ha2 = fma2(e2, wa2[j], ha2);
                hb2 = fma2(e2, wb2[j], hb2);
            }
            hbuf[wrp][e][lane]      = silu_f(hsum2(ha2) * inv8);
            hbuf[wrp][e][32 + lane] = silu_f(hsum2(hb2) * inv8);
        }
        __syncwarp();

        // ---- w = h @ Wm1 : f32x2 over K, weights reused across 4 edges ----
        unsigned long long A0[EPB], A1[EPB], A2[EPB];
#pragma unroll
        for (int e = 0; e < EPB; e++) { A0[e] = 0ull; A1[e] = 0ull; A2[e] = 0ull; }

        const float* w0p = &wm1t[lane * 68];
        const float* w1p = &wm1t[(32 + lane) * 68];
        const float* w2p = &wm1t[(64 + lane) * 68];
#pragma unroll
        for (int c = 0; c < 16; c++) {
            int k = c * 4;
            ulonglong2 q0 = *(const ulonglong2*)(w0p + k);
            ulonglong2 q1 = *(const ulonglong2*)(w1p + k);
            ulonglong2 q2 = *(const ulonglong2*)(w2p + k);
#pragma unroll
            for (int e = 0; e < EPB; e++) {
                ulonglong2 h = *(const ulonglong2*)&hbuf[wrp][e][k];
                A0[e] = fma2(h.x, q0.x, A0[e]);
                A0[e] = fma2(h.y, q0.y, A0[e]);
                A1[e] = fma2(h.x, q1.x, A1[e]);
                A1[e] = fma2(h.y, q1.y, A1[e]);
                A2[e] = fma2(h.x, q2.x, A2[e]);
                A2[e] = fma2(h.y, q2.y, A2[e]);
            }
        }
        __syncwarp();

        // ---- per-edge message using prefetched gathers + staged ea ----
#pragma unroll
        for (int e = 0; e < EPB; e++) {
            const float* eap = &eab[wrp][e * 9];
            float Y0 = eap[0];
            float z1 = y1v[e][0] * eap[1];
            z1 = fmaf(y1v[e][1], eap[2], z1);
            z1 = fmaf(y1v[e][2], eap[3], z1);
            float z2 = y2v[e][0] * eap[4];
            z2 = fmaf(y2v[e][1], eap[5], z2);
            z2 = fmaf(y2v[e][2], eap[6], z2);
            z2 = fmaf(y2v[e][3], eap[7], z2);
            z2 = fmaf(y2v[e][4], eap[8], z2);

            msgb[wrp][e][lane]      = hsum2(A0[e]) * C0 * y0v[e] * Y0;
            msgb[wrp][e][32 + lane] = hsum2(A1[e]) * C1 * z1;
            msgb[wrp][e][64 + lane] = hsum2(A2[e]) * C2 * z2;
        }
        __syncwarp();

        // ---- vector atomic scatter ----
        if (lane < 24) {
#pragma unroll
            for (int e = 0; e < EPB; e++) {
                float4 v = *(const float4*)&msgb[wrp][e][lane * 4];
                float* p = &g_mid[(size_t)didx[e] * 96 + lane * 4];
                asm volatile("red.global.add.v4.f32 [%0], {%1,%2,%3,%4};"
                             :: "l"(p), "f"(v.x), "f"(v.y), "f"(v.z), "f"(v.w)
                             : "memory");
            }
        }
        __syncwarp();
    }
}

// ---------------- Kernel 3: node finalize (transposed weights + f32x2) ----------------
__global__ void k3_kernel(const float* __restrict__ l2_0,
                          const float* __restrict__ l2_1,
                          const float* __restrict__ l2_2,
                          float* __restrict__ out)
{
    __shared__ __align__(16) float s0t[32 * 36];
    __shared__ __align__(16) float s1t[32 * 68];
    __shared__ __align__(16) float s2t[32 * 100];
    __shared__ __align__(16) float mb[8][96];

    int t = threadIdx.x;
    for (int i = t; i < 1024; i += blockDim.x) { int k = i / 32, w = i % 32; s0t[w * 36 + k]  = l2_0[i]; }
    for (int i = t; i < 2048; i += blockDim.x) { int k = i / 32, w = i % 32; s1t[w * 68 + k]  = l2_1[i]; }
    for (int i = t; i < 3072; i += blockDim.x) { int k = i / 32, w = i % 32; s2t[w * 100 + k] = l2_2[i]; }
    __syncthreads();

    int lane = t & 31;
    int wrp  = t >> 5;
    int n = (int)((blockIdx.x * blockDim.x + t) >> 5);
    if (n >= N_NODES) return;

    mb[wrp][lane]      = g_mid[n * 96 + lane];
    mb[wrp][32 + lane] = g_mid[n * 96 + 32 + lane];
    mb[wrp][64 + lane] = g_mid[n * 96 + 64 + lane];
    __syncwarp();

    unsigned long long A0 = 0ull, A1 = 0ull, A2 = 0ull, B2 = 0ull;
    const float* p0 = &s0t[lane * 36];
    const float* p1 = &s1t[lane * 68];
    const float* p2 = &s2t[lane * 100];
#pragma unroll
    for (int c = 0; c < 24; c++) {
        int k = c * 4;
        ulonglong2 m4 = *(const ulonglong2*)&mb[wrp][k];
        ulonglong2 q2 = *(const ulonglong2*)(p2 + k);
        A2 = fma2(m4.x, q2.x, A2);
        B2 = fma2(m4.y, q2.y, B2);
        if (c < 16) {
            ulonglong2 q1 = *(const ulonglong2*)(p1 + k);
            A1 = fma2(m4.x, q1.x, A1);
            A1 = fma2(m4.y, q1.y, A1);
        }
        if (c < 8) {
            ulonglong2 q0 = *(const ulonglong2*)(p0 + k);
            A0 = fma2(m4.x, q0.x, A0);
            A0 = fma2(m4.y, q0.y, A0);
        }
    }

    const float i32 = 0.17677669529663687f;
    const float i64 = 0.125f;
    const float i96 = 0.10206207261596575f;

    float o0 = silu_f(fmaf(hsum2(A0), i32, g_sc[                   n * 32 + lane]));
    float o1 = silu_f(fmaf(hsum2(A1), i64, g_sc[N_NODES * 32     + n * 32 + lane]));
    float o2 = silu_f(fmaf(hsum2(A2) + hsum2(B2), i96, g_sc[2 * N_NODES * 32 + n * 32 + lane]));

    out[                   n * 32 + lane] = o0;
    out[N_NODES * 32     + n * 32 + lane] = o1;
    out[2 * N_NODES * 32  + n * 32 + lane] = o2;
}

// ---------------- launch ----------------
extern "C" void kernel_launch(void* const* d_in, const int* in_sizes, int n_in,
                              void* d_out, int out_size)
{
    const float* x      = (const float*)d_in[0];
    const float* na     = (const float*)d_in[1];
    const float* ee     = (const float*)d_in[2];
    const float* ea     = (const float*)d_in[3];
    const int*   eidx   = (const int*)  d_in[4];
    const float* W1_0   = (const float*)d_in[5];
    const float* W1_1   = (const float*)d_in[6];
    const float* W1_2   = (const float*)d_in[7];
    const float* Wm0    = (const float*)d_in[8];
    const float* Wm1    = (const float*)d_in[9];
    const float* l2_0   = (const float*)d_in[10];
    const float* l2_1   = (const float*)d_in[11];
    const float* l2_2   = (const float*)d_in[12];
    const float* scW    = (const float*)d_in[13];
    float* out = (float*)d_out;

    k1_kernel<<<2500, 256>>>(x, na, W1_0, W1_1, W1_2, scW);
    k2_kernel<<<296, 256>>>(ee, ea, eidx, Wm0, Wm1);
    k3_kernel<<<2500, 256>>>(l2_0, l2_1, l2_2, out);
    (void)in_sizes; (void)n_in; (void)out_size;
}

// round 4
// speedup vs baseline: 1.2351x; 1.2351x over previous
#include <cuda_runtime.h>

#define N_NODES 20000
#define N_EDGES 640000
#define EPB 8   // edges per warp iteration in k2

// ---------------- scratch (static device memory, no allocation) ----------------
__device__ float g_y0 [N_NODES * 32];        // y0[n][u]
__device__ float g_y1t[N_NODES * 3 * 32];    // y1t[n][m][u]
__device__ float g_y2t[N_NODES * 5 * 32];    // y2t[n][m][u]
__device__ float g_sc [3 * N_NODES * 32];    // sc[h][n][w]
__device__ float g_mid[N_NODES * 96];        // segment-summed messages

__device__ __forceinline__ float silu_f(float x) {
    return __fdividef(x, 1.0f + __expf(-x));
}

// packed f32x2 helpers
__device__ __forceinline__ unsigned long long fma2(unsigned long long a,
                                                   unsigned long long b,
                                                   unsigned long long c) {
    unsigned long long d;
    asm("fma.rn.f32x2 %0, %1, %2, %3;" : "=l"(d) : "l"(a), "l"(b), "l"(c));
    return d;
}
__device__ __forceinline__ float hsum2(unsigned long long a) {
    float lo, hi;
    asm("mov.b64 {%0, %1}, %2;" : "=f"(lo), "=f"(hi) : "l"(a));
    return lo + hi;
}
__device__ __forceinline__ unsigned long long pack2(float lo, float hi) {
    unsigned long long p;
    asm("mov.b64 %0, {%1, %2};" : "=l"(p) : "f"(lo), "f"(hi));
    return p;
}

// ---------------- Kernel 1a: y0/y1/y2 node pre-linear, zero mid ----------------
__global__ void k1a_kernel(const float* __restrict__ x,
                           const float* __restrict__ W1_0,
                           const float* __restrict__ W1_1,
                           const float* __restrict__ W1_2)
{
    __shared__ __align__(16) float w0s[1024], w1s[1024], w2s[1024];
    int t = threadIdx.x;
    for (int i = t; i < 1024; i += blockDim.x) {
        w0s[i] = W1_0[i]; w1s[i] = W1_1[i]; w2s[i] = W1_2[i];
    }
    __syncthreads();

    int lane = t & 31;
    int n = (int)((blockIdx.x * blockDim.x + t) >> 5);
    if (n >= N_NODES) return;

    const float* xr = x + (size_t)n * 288;
    float x0r = xr[lane];
    float x1r[3], x2r[5];
#pragma unroll
    for (int m = 0; m < 3; m++) x1r[m] = xr[32 + lane * 3 + m];
#pragma unroll
    for (int m = 0; m < 5; m++) x2r[m] = xr[128 + lane * 5 + m];

    float a0 = 0.f;
    float a1[3] = {0.f, 0.f, 0.f};
    float a2[5] = {0.f, 0.f, 0.f, 0.f, 0.f};
#pragma unroll
    for (int u = 0; u < 32; u++) {
        float xv0 = __shfl_sync(0xffffffffu, x0r, u);
        a0 = fmaf(xv0, w0s[u * 32 + lane], a0);
#pragma unroll
        for (int m = 0; m < 3; m++) {
            float xv = __shfl_sync(0xffffffffu, x1r[m], u);
            a1[m] = fmaf(xv, w1s[u * 32 + lane], a1[m]);
        }
#pragma unroll
        for (int m = 0; m < 5; m++) {
            float xv = __shfl_sync(0xffffffffu, x2r[m], u);
            a2[m] = fmaf(xv, w2s[u * 32 + lane], a2[m]);
        }
    }
    const float inv = 0.17677669529663687f; // 1/sqrt(32)
    g_y0[n * 32 + lane] = a0 * inv;
#pragma unroll
    for (int m = 0; m < 3; m++) g_y1t[(n * 3 + m) * 32 + lane] = a1[m] * inv;
#pragma unroll
    for (int m = 0; m < 5; m++) g_y2t[(n * 5 + m) * 32 + lane] = a2[m] * inv;

    g_mid[n * 96 + lane]      = 0.f;
    g_mid[n * 96 + 32 + lane] = 0.f;
    g_mid[n * 96 + 64 + lane] = 0.f;
}

// ---------------- Kernel 1b: self-connection sc ----------------
__global__ void k1b_kernel(const float* __restrict__ x,
                           const float* __restrict__ na,
                           const float* __restrict__ scW)
{
    __shared__ __align__(16) float s[12288]; // 48KB
    int t = threadIdx.x;
    for (int i = t; i < 12288; i += blockDim.x) s[i] = scW[i];
    __syncthreads();

    int lane = t & 31;
    int n = (int)((blockIdx.x * blockDim.x + t) >> 5);
    if (n >= N_NODES) return;

    float x0r = x[(size_t)n * 288 + lane];
    float nar = (lane < 4) ? na[n * 4 + lane] : 0.f;
    float na0 = __shfl_sync(0xffffffffu, nar, 0);
    float na1 = __shfl_sync(0xffffffffu, nar, 1);
    float na2 = __shfl_sync(0xffffffffu, nar, 2);
    float na3 = __shfl_sync(0xffffffffu, nar, 3);

    float acc[3] = {0.f, 0.f, 0.f};
#pragma unroll
    for (int u = 0; u < 32; u++) {
        float x0u = __shfl_sync(0xffffffffu, x0r, u);
        float c0 = x0u * na0, c1 = x0u * na1, c2 = x0u * na2, c3 = x0u * na3;
#pragma unroll
        for (int h = 0; h < 3; h++) {
            const float* p = s + ((h * 32 + u) * 4) * 32 + lane;
            acc[h] = fmaf(c0, p[0],  acc[h]);
            acc[h] = fmaf(c1, p[32], acc[h]);
            acc[h] = fmaf(c2, p[64], acc[h]);
            acc[h] = fmaf(c3, p[96], acc[h]);
        }
    }
    const float invs = 0.08838834764831845f; // 1/sqrt(128)
#pragma unroll
    for (int h = 0; h < 3; h++)
        g_sc[h * (N_NODES * 32) + n * 32 + lane] = acc[h] * invs;
}

// ---------------- Kernel 2: fused edge MLP + gather + message + scatter ----------------
// warp processes EPB=8 edges/iter; lane = channel. Weights amortized over 8 edges.
__global__ void __launch_bounds__(256, 2) k2_kernel(const float* __restrict__ ee,
                          const float* __restrict__ ea,
                          const int*   __restrict__ eidx,
                          const float* __restrict__ Wm0,
                          const float* __restrict__ Wm1)
{
    __shared__ __align__(16) float wm1t[96 * 68];        // [c][k], stride 68
    __shared__ __align__(16) float hbuf[8][EPB][64];     // per-warp h
    __shared__ __align__(16) float msgb[8][EPB][96];     // per-warp messages
    __shared__ __align__(16) float eeb [8][EPB * 8];     // staged edge_embed
    __shared__ __align__(16) float eab [8][EPB * 9];     // staged edge_attrs

    int t = threadIdx.x;
    for (int i = t; i < 64 * 96; i += blockDim.x) {
        int j = i / 96, c = i % 96;
        wm1t[c * 68 + j] = Wm1[i];
    }
    __syncthreads();

    int lane = t & 31;
    int wrp  = t >> 5;

    const float inv8 = 0.35355339059327373f;            // 1/sqrt(8)
    // Wm0 packed over k-pairs, pre-scaled by 1/sqrt(8)
    unsigned long long wa2[4], wb2[4];
#pragma unroll
    for (int j = 0; j < 4; j++) {
        wa2[j] = pack2(Wm0[(2 * j) * 64 + lane] * inv8,      Wm0[(2 * j + 1) * 64 + lane] * inv8);
        wb2[j] = pack2(Wm0[(2 * j) * 64 + 32 + lane] * inv8, Wm0[(2 * j + 1) * 64 + 32 + lane] * inv8);
    }

    const float C0 = 0.125f * 0.17677669529663687f;     // invh*savg
    const float C1 = C0 * 0.5773502691896258f;          // *1/sqrt3
    const float C2 = C0 * 0.4472135954999579f;          // *1/sqrt5

    int warpid = blockIdx.x * 8 + wrp;
    int nwarp  = gridDim.x * 8;
    const int niter = N_EDGES / EPB;

    for (int it = warpid; it < niter; it += nwarp) {
        int ebase = it * EPB;

        // ---- stage ee (64 floats) + ea (72 floats) coalesced ----
        {
            float2 v = *(const float2*)&ee[(size_t)ebase * 8 + lane * 2];
            *(float2*)&eeb[wrp][lane * 2] = v;
            float2 w = *(const float2*)&ea[(size_t)ebase * 9 + lane * 2];
            *(float2*)&eab[wrp][lane * 2] = w;
            if (lane < 4) {
                float2 u = *(const float2*)&ea[(size_t)ebase * 9 + 64 + lane * 2];
                *(float2*)&eab[wrp][64 + lane * 2] = u;
            }
        }
        __syncwarp();

        // ---- h = silu(ee @ Wm0 * inv8) for 8 edges ----
#pragma unroll
        for (int e = 0; e < EPB; e++) {
            const float* eep = &eeb[wrp][e * 8];
            ulonglong2 e01 = *(const ulonglong2*)eep;
            ulonglong2 e23 = *(const ulonglong2*)(eep + 4);
            unsigned long long ha2 = 0ull, hb2 = 0ull;
            ha2 = fma2(e01.x, wa2[0], ha2);  hb2 = fma2(e01.x, wb2[0], hb2);
            ha2 = fma2(e01.y, wa2[1], ha2);  hb2 = fma2(e01.y, wb2[1], hb2);
            ha2 = fma2(e23.x, wa2[2], ha2);  hb2 = fma2(e23.x, wb2[2], hb2);
            ha2 = fma2(e23.y, wa2[3], ha2);  hb2 = fma2(e23.y, wb2[3], hb2);
            hbuf[wrp][e][lane]      = silu_f(hsum2(ha2));
            hbuf[wrp][e][32 + lane] = silu_f(hsum2(hb2));
        }
        __syncwarp();

        // ---- w = h @ Wm1 : f32x2 over K, weights reused across 8 edges ----
        unsigned long long A0[EPB], A1[EPB], A2[EPB];
#pragma unroll
        for (int e = 0; e < EPB; e++) { A0[e] = 0ull; A1[e] = 0ull; A2[e] = 0ull; }

        const float* w0p = &wm1t[lane * 68];
        const float* w1p = &wm1t[(32 + lane) * 68];
        const float* w2p = &wm1t[(64 + lane) * 68];
#pragma unroll
        for (int c = 0; c < 16; c++) {
            int k = c * 4;
            ulonglong2 q0 = *(const ulonglong2*)(w0p + k);
            ulonglong2 q1 = *(const ulonglong2*)(w1p + k);
            ulonglong2 q2 = *(const ulonglong2*)(w2p + k);
#pragma unroll
            for (int e = 0; e < EPB; e++) {
                ulonglong2 h = *(const ulonglong2*)&hbuf[wrp][e][k];
                A0[e] = fma2(h.x, q0.x, A0[e]);
                A0[e] = fma2(h.y, q0.y, A0[e]);
                A1[e] = fma2(h.x, q1.x, A1[e]);
                A1[e] = fma2(h.y, q1.y, A1[e]);
                A2[e] = fma2(h.x, q2.x, A2[e]);
                A2[e] = fma2(h.y, q2.y, A2[e]);
            }
        }
        __syncwarp();

        // ---- per-edge gather+message, 2-stage pipeline on gathers ----
        float py0, py1[3], py2[5];
        {
            int s0 = __ldg(&eidx[ebase]);
            py0 = __ldg(g_y0 + (size_t)s0 * 32 + lane);
#pragma unroll
            for (int m = 0; m < 3; m++) py1[m] = __ldg(g_y1t + (size_t)s0 * 96 + m * 32 + lane);
#pragma unroll
            for (int m = 0; m < 5; m++) py2[m] = __ldg(g_y2t + (size_t)s0 * 160 + m * 32 + lane);
        }
#pragma unroll
        for (int e = 0; e < EPB; e++) {
            float cy0 = py0, cy1[3], cy2[5];
#pragma unroll
            for (int m = 0; m < 3; m++) cy1[m] = py1[m];
#pragma unroll
            for (int m = 0; m < 5; m++) cy2[m] = py2[m];
            if (e + 1 < EPB) {
                int sn = __ldg(&eidx[ebase + e + 1]);
                py0 = __ldg(g_y0 + (size_t)sn * 32 + lane);
#pragma unroll
                for (int m = 0; m < 3; m++) py1[m] = __ldg(g_y1t + (size_t)sn * 96 + m * 32 + lane);
#pragma unroll
                for (int m = 0; m < 5; m++) py2[m] = __ldg(g_y2t + (size_t)sn * 160 + m * 32 + lane);
            }
            const float* eap = &eab[wrp][e * 9];
            float Y0 = eap[0];
            float z1 = cy1[0] * eap[1];
            z1 = fmaf(cy1[1], eap[2], z1);
            z1 = fmaf(cy1[2], eap[3], z1);
            float z2 = cy2[0] * eap[4];
            z2 = fmaf(cy2[1], eap[5], z2);
            z2 = fmaf(cy2[2], eap[6], z2);
            z2 = fmaf(cy2[3], eap[7], z2);
            z2 = fmaf(cy2[4], eap[8], z2);

            msgb[wrp][e][lane]      = hsum2(A0[e]) * C0 * cy0 * Y0;
            msgb[wrp][e][32 + lane] = hsum2(A1[e]) * C1 * z1;
            msgb[wrp][e][64 + lane] = hsum2(A2[e]) * C2 * z2;
        }
        __syncwarp();

        // ---- vector atomic scatter ----
        if (lane < 24) {
#pragma unroll
            for (int e = 0; e < EPB; e++) {
                int d = __ldg(&eidx[N_EDGES + ebase + e]);
                float4 v = *(const float4*)&msgb[wrp][e][lane * 4];
                float* p = &g_mid[(size_t)d * 96 + lane * 4];
                asm volatile("red.global.add.v4.f32 [%0], {%1,%2,%3,%4};"
                             :: "l"(p), "f"(v.x), "f"(v.y), "f"(v.z), "f"(v.w)
                             : "memory");
            }
        }
        __syncwarp();
    }
}

// ---------------- Kernel 3: node finalize (transposed weights + f32x2) ----------------
__global__ void k3_kernel(const float* __restrict__ l2_0,
                          const float* __restrict__ l2_1,
                          const float* __restrict__ l2_2,
                          float* __restrict__ out)
{
    __shared__ __align__(16) float s0t[32 * 36];
    __shared__ __align__(16) float s1t[32 * 68];
    __shared__ __align__(16) float s2t[32 * 100];
    __shared__ __align__(16) float mb[8][96];

    int t = threadIdx.x;
    for (int i = t; i < 1024; i += blockDim.x) { int k = i / 32, w = i % 32; s0t[w * 36 + k]  = l2_0[i]; }
    for (int i = t; i < 2048; i += blockDim.x) { int k = i / 32, w = i % 32; s1t[w * 68 + k]  = l2_1[i]; }
    for (int i = t; i < 3072; i += blockDim.x) { int k = i / 32, w = i % 32; s2t[w * 100 + k] = l2_2[i]; }
    __syncthreads();

    int lane = t & 31;
    int wrp  = t >> 5;
    int n = (int)((blockIdx.x * blockDim.x + t) >> 5);
    if (n >= N_NODES) return;

    mb[wrp][lane]      = g_mid[n * 96 + lane];
    mb[wrp][32 + lane] = g_mid[n * 96 + 32 + lane];
    mb[wrp][64 + lane] = g_mid[n * 96 + 64 + lane];
    __syncwarp();

    unsigned long long A0 = 0ull, A1 = 0ull, A2 = 0ull, B2 = 0ull;
    const float* p0 = &s0t[lane * 36];
    const float* p1 = &s1t[lane * 68];
    const float* p2 = &s2t[lane * 100];
#pragma unroll
    for (int c = 0; c < 24; c++) {
        int k = c * 4;
        ulonglong2 m4 = *(const ulonglong2*)&mb[wrp][k];
        ulonglong2 q2 = *(const ulonglong2*)(p2 + k);
        A2 = fma2(m4.x, q2.x, A2);
        B2 = fma2(m4.y, q2.y, B2);
        if (c < 16) {
            ulonglong2 q1 = *(const ulonglong2*)(p1 + k);
            A1 = fma2(m4.x, q1.x, A1);
            A1 = fma2(m4.y, q1.y, A1);
        }
        if (c < 8) {
            ulonglong2 q0 = *(const ulonglong2*)(p0 + k);
            A0 = fma2(m4.x, q0.x, A0);
            A0 = fma2(m4.y, q0.y, A0);
        }
    }

    const float i32 = 0.17677669529663687f;
    const float i64 = 0.125f;
    const float i96 = 0.10206207261596575f;

    float o0 = silu_f(fmaf(hsum2(A0), i32, g_sc[                   n * 32 + lane]));
    float o1 = silu_f(fmaf(hsum2(A1), i64, g_sc[N_NODES * 32     + n * 32 + lane]));
    float o2 = silu_f(fmaf(hsum2(A2) + hsum2(B2), i96, g_sc[2 * N_NODES * 32 + n * 32 + lane]));

    out[                   n * 32 + lane] = o0;
    out[N_NODES * 32     + n * 32 + lane] = o1;
    out[2 * N_NODES * 32  + n * 32 + lane] = o2;
}

// ---------------- launch ----------------
extern "C" void kernel_launch(void* const* d_in, const int* in_sizes, int n_in,
                              void* d_out, int out_size)
{
    const float* x      = (const float*)d_in[0];
    const float* na     = (const float*)d_in[1];
    const float* ee     = (const float*)d_in[2];
    const float* ea     = (const float*)d_in[3];
    const int*   eidx   = (const int*)  d_in[4];
    const float* W1_0   = (const float*)d_in[5];
    const float* W1_1   = (const float*)d_in[6];
    const float* W1_2   = (const float*)d_in[7];
    const float* Wm0    = (const float*)d_in[8];
    const float* Wm1    = (const float*)d_in[9];
    const float* l2_0   = (const float*)d_in[10];
    const float* l2_1   = (const float*)d_in[11];
    const float* l2_2   = (const float*)d_in[12];
    const float* scW    = (const float*)d_in[13];
    float* out = (float*)d_out;

    k1a_kernel<<<2500, 256>>>(x, W1_0, W1_1, W1_2);
    k1b_kernel<<<2500, 256>>>(x, na, scW);
    k2_kernel<<<296, 256>>>(ee, ea, eidx, Wm0, Wm1);
    k3_kernel<<<2500, 256>>>(l2_0, l2_1, l2_2, out);
    (void)in_sizes; (void)n_in; (void)out_size;
}

// round 6
// speedup vs baseline: 1.3296x; 1.0765x over previous
#include <cuda_runtime.h>
#include <cuda_bf16.h>
#include <cstdint>

#define N_NODES 20000
#define N_EDGES 640000
#define K2_BLOCKS 444
#define K2_SMEM 73472

// ---------------- scratch (static device memory, no allocation) ----------------
__device__ float g_y0 [N_NODES * 32];        // y0[n][u]
__device__ float g_y1t[N_NODES * 3 * 32];    // y1t[n][m][u]
__device__ float g_y2t[N_NODES * 5 * 32];    // y2t[n][m][u]
__device__ float g_sc [3 * N_NODES * 32];    // sc[h][n][w]
__device__ float g_mid[N_NODES * 96];        // segment-summed messages

__device__ __forceinline__ float silu_f(float x) {
    return __fdividef(x, 1.0f + __expf(-x));
}
__device__ __forceinline__ unsigned long long fma2(unsigned long long a,
                                                   unsigned long long b,
                                                   unsigned long long c) {
    unsigned long long d;
    asm("fma.rn.f32x2 %0, %1, %2, %3;" : "=l"(d) : "l"(a), "l"(b), "l"(c));
    return d;
}
__device__ __forceinline__ unsigned long long pack2(float lo, float hi) {
    unsigned long long p;
    asm("mov.b64 %0, {%1, %2};" : "=l"(p) : "f"(lo), "f"(hi));
    return p;
}
__device__ __forceinline__ uint32_t smem_u32(const void* p) {
    uint32_t a;
    asm("{ .reg .u64 t; cvta.to.shared.u64 t, %1; cvt.u32.u64 %0, t; }" : "=r"(a) : "l"(p));
    return a;
}

// ---------------- Kernel 1a: y0/y1/y2 node pre-linear, zero mid ----------------
__global__ void k1a_kernel(const float* __restrict__ x,
                           const float* __restrict__ W1_0,
                           const float* __restrict__ W1_1,
                           const float* __restrict__ W1_2)
{
    __shared__ __align__(16) float w0s[1024], w1s[1024], w2s[1024];
    int t = threadIdx.x;
    for (int i = t; i < 1024; i += blockDim.x) {
        w0s[i] = W1_0[i]; w1s[i] = W1_1[i]; w2s[i] = W1_2[i];
    }
    __syncthreads();

    int lane = t & 31;
    int n = (int)((blockIdx.x * blockDim.x + t) >> 5);
    if (n >= N_NODES) return;

    const float* xr = x + (size_t)n * 288;
    float x0r = xr[lane];
    float x1r[3], x2r[5];
#pragma unroll
    for (int m = 0; m < 3; m++) x1r[m] = xr[32 + lane * 3 + m];
#pragma unroll
    for (int m = 0; m < 5; m++) x2r[m] = xr[128 + lane * 5 + m];

    float a0 = 0.f;
    float a1[3] = {0.f, 0.f, 0.f};
    float a2[5] = {0.f, 0.f, 0.f, 0.f, 0.f};
#pragma unroll
    for (int u = 0; u < 32; u++) {
        float xv0 = __shfl_sync(0xffffffffu, x0r, u);
        a0 = fmaf(xv0, w0s[u * 32 + lane], a0);
#pragma unroll
        for (int m = 0; m < 3; m++) {
            float xv = __shfl_sync(0xffffffffu, x1r[m], u);
            a1[m] = fmaf(xv, w1s[u * 32 + lane], a1[m]);
        }
#pragma unroll
        for (int m = 0; m < 5; m++) {
            float xv = __shfl_sync(0xffffffffu, x2r[m], u);
            a2[m] = fmaf(xv, w2s[u * 32 + lane], a2[m]);
        }
    }
    const float inv = 0.17677669529663687f; // 1/sqrt(32)
    g_y0[n * 32 + lane] = a0 * inv;
#pragma unroll
    for (int m = 0; m < 3; m++) g_y1t[(n * 3 + m) * 32 + lane] = a1[m] * inv;
#pragma unroll
    for (int m = 0; m < 5; m++) g_y2t[(n * 5 + m) * 32 + lane] = a2[m] * inv;

    g_mid[n * 96 + lane]      = 0.f;
    g_mid[n * 96 + 32 + lane] = 0.f;
    g_mid[n * 96 + 64 + lane] = 0.f;
}

// ---------------- Kernel 1b: self-connection sc ----------------
__global__ void k1b_kernel(const float* __restrict__ x,
                           const float* __restrict__ na,
                           const float* __restrict__ scW)
{
    __shared__ __align__(16) float s[12288]; // 48KB
    int t = threadIdx.x;
    for (int i = t; i < 12288; i += blockDim.x) s[i] = scW[i];
    __syncthreads();

    int lane = t & 31;
    int n = (int)((blockIdx.x * blockDim.x + t) >> 5);
    if (n >= N_NODES) return;

    float x0r = x[(size_t)n * 288 + lane];
    float nar = (lane < 4) ? na[n * 4 + lane] : 0.f;
    float na0 = __shfl_sync(0xffffffffu, nar, 0);
    float na1 = __shfl_sync(0xffffffffu, nar, 1);
    float na2 = __shfl_sync(0xffffffffu, nar, 2);
    float na3 = __shfl_sync(0xffffffffu, nar, 3);

    float acc[3] = {0.f, 0.f, 0.f};
#pragma unroll
    for (int u = 0; u < 32; u++) {
        float x0u = __shfl_sync(0xffffffffu, x0r, u);
        float c0 = x0u * na0, c1 = x0u * na1, c2 = x0u * na2, c3 = x0u * na3;
#pragma unroll
        for (int h = 0; h < 3; h++) {
            const float* p = s + ((h * 32 + u) * 4) * 32 + lane;
            acc[h] = fmaf(c0, p[0],  acc[h]);
            acc[h] = fmaf(c1, p[32], acc[h]);
            acc[h] = fmaf(c2, p[64], acc[h]);
            acc[h] = fmaf(c3, p[96], acc[h]);
        }
    }
    const float invs = 0.08838834764831845f; // 1/sqrt(128)
#pragma unroll
    for (int h = 0; h < 3; h++)
        g_sc[h * (N_NODES * 32) + n * 32 + lane] = acc[h] * invs;
}

// ---------------- Kernel 2: mma.sync (HMMA bf16 split) edge pipeline ----------------
// 128 threads = 4 warps; each warp owns 16 edges per iteration, fully independent.
// smem: wm0s f32[512] | W bf16[96][136] (hi cols 0-63, lo 64-127) |
//       H bf16[4][16][136] | wsm f32[4][16][100] | ea f32[4][144]
__global__ void __launch_bounds__(128, 3) k2_kernel(const float* __restrict__ ee,
                          const float* __restrict__ ea,
                          const int*   __restrict__ eidx,
                          const float* __restrict__ Wm0,
                          const float* __restrict__ Wm1)
{
    extern __shared__ __align__(16) unsigned char smraw[];
    float*          wm0s = (float*)smraw;                          // [0, 2048)
    __nv_bfloat16*  Wb   = (__nv_bfloat16*)(smraw + 2048);         // [2048, 28160)
    float*          wsm  = (float*)(smraw + 45568);                // [45568, 71168)
    float*          ea_s = (float*)(smraw + 71168);                // [71168, 73472)

    const uint32_t sb    = smem_u32(smraw);
    const uint32_t W_u32 = sb + 2048;
    const uint32_t H_u32 = sb + 28160;

    int tid  = threadIdx.x;
    int lane = tid & 31;
    int wrp  = tid >> 5;

    const float inv8 = 0.35355339059327373f;          // 1/sqrt(8)
    const float C0 = 0.125f * 0.17677669529663687f;   // invh*savg
    const float C1 = C0 * 0.5773502691896258f;        // *1/sqrt3
    const float C2 = C0 * 0.4472135954999579f;        // *1/sqrt5

    // one-time: scaled Wm0
    for (int i = tid; i < 512; i += 128) wm0s[i] = Wm0[i] * inv8;
    // one-time: split-bf16 of Wm1 with column scales folded; rows = n, k contiguous
    for (int i = tid; i < 96 * 64; i += 128) {
        int n = i >> 6, k = i & 63;
        float Cn = (n < 32) ? C0 : (n < 64) ? C1 : C2;
        float w = Wm1[k * 96 + n] * Cn;
        __nv_bfloat16 hb = __float2bfloat16(w);
        Wb[n * 136 + k]      = hb;
        Wb[n * 136 + 64 + k] = __float2bfloat16(w - __bfloat162float(hb));
    }
    __syncthreads();

    float* ea_w  = ea_s + wrp * 144;
    float* wsm_w = wsm + wrp * 1600;
    const uint32_t Hw = H_u32 + wrp * 4352;

    int eloc = lane >> 1, half = lane & 1;
    const float* wp = wm0s + (half << 5);

    // ldmatrix lane address bases
    const uint32_t a_base = Hw + (uint32_t)(lane & 15) * 272 + (uint32_t)((lane >> 4) & 1) * 16;
    const uint32_t b_base = W_u32 + (uint32_t)(lane & 7) * 272 + (uint32_t)((lane >> 3) & 1) * 16;

    const uint32_t hrow = Hw + (uint32_t)eloc * 272 + (uint32_t)half * 64;

    int wg = blockIdx.x * 4 + wrp;
    int nw = gridDim.x * 4;

    for (int g = wg; g < N_EDGES / 16; g += nw) {
        int base = g * 16;

        // ---- stage edge attrs ----
        for (int i = lane; i < 144; i += 32)
            ea_w[i] = __ldg(ea + (size_t)base * 9 + i);

        // ---- first MLP: 2 lanes per edge, 32 channels each ----
        float ev[8];
        {
            const float4* p = (const float4*)(ee + (size_t)(base + eloc) * 8);
            float4 va = __ldg(p), vb = __ldg(p + 1);
            ev[0]=va.x; ev[1]=va.y; ev[2]=va.z; ev[3]=va.w;
            ev[4]=vb.x; ev[5]=vb.y; ev[6]=vb.z; ev[7]=vb.w;
        }
        unsigned long long hacc[16];
#pragma unroll
        for (int j = 0; j < 16; j++) hacc[j] = 0ull;
#pragma unroll
        for (int k = 0; k < 8; k++) {
            unsigned long long ek2 = pack2(ev[k], ev[k]);
            const ulonglong2* q = (const ulonglong2*)(wp + (k << 6));
#pragma unroll
            for (int j = 0; j < 8; j++) {
                ulonglong2 v = q[j];
                hacc[2 * j]     = fma2(ek2, v.x, hacc[2 * j]);
                hacc[2 * j + 1] = fma2(ek2, v.y, hacc[2 * j + 1]);
            }
        }
        // silu + bf16 split + store H (hi at col, lo at col+64)
#pragma unroll
        for (int j = 0; j < 16; j++) {
            float s0, s1;
            asm("mov.b64 {%0,%1}, %2;" : "=f"(s0), "=f"(s1) : "l"(hacc[j]));
            s0 = silu_f(s0); s1 = silu_f(s1);
            uint32_t hb;
            asm("cvt.rn.bf16x2.f32 %0, %1, %2;" : "=r"(hb) : "f"(s1), "f"(s0));
            float f0 = __uint_as_float(hb << 16);
            float f1 = __uint_as_float(hb & 0xFFFF0000u);
            float r0 = s0 - f0, r1 = s1 - f1;
            uint32_t lb;
            asm("cvt.rn.bf16x2.f32 %0, %1, %2;" : "=r"(lb) : "f"(r1), "f"(r0));
            asm volatile("st.shared.b32 [%0], %1;" :: "r"(hrow + j * 4), "r"(hb) : "memory");
            asm volatile("st.shared.b32 [%0], %1;" :: "r"(hrow + 128 + j * 4), "r"(lb) : "memory");
        }
        __syncwarp();

        // ---- GEMM: D[16,96] = Hhi*Whi + Hlo*Whi + Hhi*Wlo ----
        float acc[48];
#pragma unroll
        for (int i = 0; i < 48; i++) acc[i] = 0.f;
#pragma unroll
        for (int k = 0; k < 4; k++) {
            uint32_t ah0, ah1, ah2, ah3, al0, al1, al2, al3;
            asm volatile("ldmatrix.sync.aligned.m8n8.x4.shared.b16 {%0,%1,%2,%3}, [%4];"
                         : "=r"(ah0), "=r"(ah1), "=r"(ah2), "=r"(ah3)
                         : "r"(a_base + k * 32));
            asm volatile("ldmatrix.sync.aligned.m8n8.x4.shared.b16 {%0,%1,%2,%3}, [%4];"
                         : "=r"(al0), "=r"(al1), "=r"(al2), "=r"(al3)
                         : "r"(a_base + 128 + k * 32));
#pragma unroll
            for (int n = 0; n < 12; n++) {
                uint32_t baddr = b_base + (uint32_t)n * 2176 + k * 32;
                uint32_t bh0, bh1, bl0, bl1;
                asm volatile("ldmatrix.sync.aligned.m8n8.x2.shared.b16 {%0,%1}, [%2];"
                             : "=r"(bh0), "=r"(bh1) : "r"(baddr));
                asm volatile("ldmatrix.sync.aligned.m8n8.x2.shared.b16 {%0,%1}, [%2];"
                             : "=r"(bl0), "=r"(bl1) : "r"(baddr + 128));
                float* d = acc + n * 4;
                asm volatile("mma.sync.aligned.m16n8k16.row.col.f32.bf16.bf16.f32 "
                             "{%0,%1,%2,%3}, {%4,%5,%6,%7}, {%8,%9}, {%0,%1,%2,%3};"
                             : "+f"(d[0]), "+f"(d[1]), "+f"(d[2]), "+f"(d[3])
                             : "r"(ah0), "r"(ah1), "r"(ah2), "r"(ah3), "r"(bh0), "r"(bh1));
                asm volatile("mma.sync.aligned.m16n8k16.row.col.f32.bf16.bf16.f32 "
                             "{%0,%1,%2,%3}, {%4,%5,%6,%7}, {%8,%9}, {%0,%1,%2,%3};"
                             : "+f"(d[0]), "+f"(d[1]), "+f"(d[2]), "+f"(d[3])
                             : "r"(al0), "r"(al1), "r"(al2), "r"(al3), "r"(bh0), "r"(bh1));
                asm volatile("mma.sync.aligned.m16n8k16.row.col.f32.bf16.bf16.f32 "
                             "{%0,%1,%2,%3}, {%4,%5,%6,%7}, {%8,%9}, {%0,%1,%2,%3};"
                             : "+f"(d[0]), "+f"(d[1]), "+f"(d[2]), "+f"(d[3])
                             : "r"(ah0), "r"(ah1), "r"(ah2), "r"(ah3), "r"(bl0), "r"(bl1));
            }
        }

        // ---- stage D to smem: thread holds rows (g, g+8), cols n*8+2t ----
        {
            int gq = lane >> 2, tg = lane & 3;
#pragma unroll
            for (int n = 0; n < 12; n++) {
                int col = n * 8 + tg * 2;
                *(float2*)&wsm_w[gq * 100 + col]       = make_float2(acc[n * 4],     acc[n * 4 + 1]);
                *(float2*)&wsm_w[(gq + 8) * 100 + col] = make_float2(acc[n * 4 + 2], acc[n * 4 + 3]);
            }
        }
        __syncwarp();

        // ---- tail: lane = channel, 16 edges ----
#pragma unroll 4
        for (int le = 0; le < 16; le++) {
            int s = __ldg(eidx + base + le);
            const float* eap = ea_w + le * 9;
            float* wr = wsm_w + le * 100;
            float w0 = wr[lane], w1 = wr[32 + lane], w2 = wr[64 + lane];

            float y0v = __ldg(g_y0 + (size_t)s * 32 + lane);
            float z1 = __ldg(g_y1t + (size_t)s * 96 + lane) * eap[1];
            z1 = fmaf(__ldg(g_y1t + (size_t)s * 96 + 32 + lane), eap[2], z1);
            z1 = fmaf(__ldg(g_y1t + (size_t)s * 96 + 64 + lane), eap[3], z1);
            float z2 = __ldg(g_y2t + (size_t)s * 160 + lane) * eap[4];
            z2 = fmaf(__ldg(g_y2t + (size_t)s * 160 + 32 + lane),  eap[5], z2);
            z2 = fmaf(__ldg(g_y2t + (size_t)s * 160 + 64 + lane),  eap[6], z2);
            z2 = fmaf(__ldg(g_y2t + (size_t)s * 160 + 96 + lane),  eap[7], z2);
            z2 = fmaf(__ldg(g_y2t + (size_t)s * 160 + 128 + lane), eap[8], z2);

            wr[lane]      = w0 * y0v * eap[0];
            wr[32 + lane] = w1 * z1;
            wr[64 + lane] = w2 * z2;
        }
        __syncwarp();

        // ---- vector atomic scatter ----
        if (lane < 24) {
#pragma unroll 4
            for (int le = 0; le < 16; le++) {
                int d = __ldg(eidx + N_EDGES + base + le);
                float4 v = *(const float4*)&wsm_w[le * 100 + lane * 4];
                float* p = &g_mid[(size_t)d * 96 + lane * 4];
                asm volatile("red.global.add.v4.f32 [%0], {%1,%2,%3,%4};"
                             :: "l"(p), "f"(v.x), "f"(v.y), "f"(v.z), "f"(v.w)
                             : "memory");
            }
        }
        __syncwarp();
    }
}

// ---------------- Kernel 3: node finalize (transposed weights + f32x2) ----------------
__global__ void k3_kernel(const float* __restrict__ l2_0,
                          const float* __restrict__ l2_1,
                          const float* __restrict__ l2_2,
                          float* __restrict__ out)
{
    __shared__ __align__(16) float s0t[32 * 36];
    __shared__ __align__(16) float s1t[32 * 68];
    __shared__ __align__(16) float s2t[32 * 100];
    __shared__ __align__(16) float mb[8][96];

    int t = threadIdx.x;
    for (int i = t; i < 1024; i += blockDim.x) { int k = i / 32, w = i % 32; s0t[w * 36 + k]  = l2_0[i]; }
    for (int i = t; i < 2048; i += blockDim.x) { int k = i / 32, w = i % 32; s1t[w * 68 + k]  = l2_1[i]; }
    for (int i = t; i < 3072; i += blockDim.x) { int k = i / 32, w = i % 32; s2t[w * 100 + k] = l2_2[i]; }
    __syncthreads();

    int lane = t & 31;
    int wrp  = t >> 5;
    int n = (int)((blockIdx.x * blockDim.x + t) >> 5);
    if (n >= N_NODES) return;

    mb[wrp][lane]      = g_mid[n * 96 + lane];
    mb[wrp][32 + lane] = g_mid[n * 96 + 32 + lane];
    mb[wrp][64 + lane] = g_mid[n * 96 + 64 + lane];
    __syncwarp();

    unsigned long long A0 = 0ull, A1 = 0ull, A2 = 0ull, B2 = 0ull;
    const float* p0 = &s0t[lane * 36];
    const float* p1 = &s1t[lane * 68];
    const float* p2 = &s2t[lane * 100];
#pragma unroll
    for (int c = 0; c < 24; c++) {
        int k = c * 4;
        ulonglong2 m4 = *(const ulonglong2*)&mb[wrp][k];
        ulonglong2 q2 = *(const ulonglong2*)(p2 + k);
        A2 = fma2(m4.x, q2.x, A2);
        B2 = fma2(m4.y, q2.y, B2);
        if (c < 16) {
            ulonglong2 q1 = *(const ulonglong2*)(p1 + k);
            A1 = fma2(m4.x, q1.x, A1);
            A1 = fma2(m4.y, q1.y, A1);
        }
        if (c < 8) {
            ulonglong2 q0 = *(const ulonglong2*)(p0 + k);
            A0 = fma2(m4.x, q0.x, A0);
            A0 = fma2(m4.y, q0.y, A0);
        }
    }

    const float i32 = 0.17677669529663687f;
    const float i64 = 0.125f;
    const float i96 = 0.10206207261596575f;

    float a0lo, a0hi, a1lo, a1hi, a2lo, a2hi, b2lo, b2hi;
    asm("mov.b64 {%0,%1}, %2;" : "=f"(a0lo), "=f"(a0hi) : "l"(A0));
    asm("mov.b64 {%0,%1}, %2;" : "=f"(a1lo), "=f"(a1hi) : "l"(A1));
    asm("mov.b64 {%0,%1}, %2;" : "=f"(a2lo), "=f"(a2hi) : "l"(A2));
    asm("mov.b64 {%0,%1}, %2;" : "=f"(b2lo), "=f"(b2hi) : "l"(B2));

    float o0 = silu_f(fmaf(a0lo + a0hi, i32, g_sc[                   n * 32 + lane]));
    float o1 = silu_f(fmaf(a1lo + a1hi, i64, g_sc[N_NODES * 32     + n * 32 + lane]));
    float o2 = silu_f(fmaf((a2lo + a2hi) + (b2lo + b2hi), i96, g_sc[2 * N_NODES * 32 + n * 32 + lane]));

    out[                   n * 32 + lane] = o0;
    out[N_NODES * 32     + n * 32 + lane] = o1;
    out[2 * N_NODES * 32  + n * 32 + lane] = o2;
}

// ---------------- launch ----------------
extern "C" void kernel_launch(void* const* d_in, const int* in_sizes, int n_in,
                              void* d_out, int out_size)
{
    const float* x      = (const float*)d_in[0];
    const float* na     = (const float*)d_in[1];
    const float* ee     = (const float*)d_in[2];
    const float* ea     = (const float*)d_in[3];
    const int*   eidx   = (const int*)  d_in[4];
    const float* W1_0   = (const float*)d_in[5];
    const float* W1_1   = (const float*)d_in[6];
    const float* W1_2   = (const float*)d_in[7];
    const float* Wm0    = (const float*)d_in[8];
    const float* Wm1    = (const float*)d_in[9];
    const float* l2_0   = (const float*)d_in[10];
    const float* l2_1   = (const float*)d_in[11];
    const float* l2_2   = (const float*)d_in[12];
    const float* scW    = (const float*)d_in[13];
    float* out = (float*)d_out;

    cudaFuncSetAttribute(k2_kernel, cudaFuncAttributeMaxDynamicSharedMemorySize, K2_SMEM);

    k1a_kernel<<<2500, 256>>>(x, W1_0, W1_1, W1_2);
    k1b_kernel<<<2500, 256>>>(x, na, scW);
    k2_kernel<<<K2_BLOCKS, 128, K2_SMEM>>>(ee, ea, eidx, Wm0, Wm1);
    k3_kernel<<<2500, 256>>>(l2_0, l2_1, l2_2, out);
    (void)in_sizes; (void)n_in; (void)out_size;
}

// round 7
// speedup vs baseline: 1.3903x; 1.0457x over previous
#include <cuda_runtime.h>
#include <cuda_bf16.h>
#include <cstdint>

#define N_NODES 20000
#define N_EDGES 640000
#define K2_BLOCKS 444
#define K2_SMEM 73472

// ---------------- scratch (static device memory, no allocation) ----------------
__device__ float g_y0 [N_NODES * 32];        // y0[n][u]
__device__ float g_y1t[N_NODES * 3 * 32];    // y1t[n][m][u]
__device__ float g_y2t[N_NODES * 5 * 32];    // y2t[n][m][u]
__device__ float g_sc [3 * N_NODES * 32];    // sc[h][n][w]
__device__ float g_mid[N_NODES * 96];        // segment-summed messages

__device__ __forceinline__ float silu_f(float x) {
    return __fdividef(x, 1.0f + __expf(-x));
}
__device__ __forceinline__ unsigned long long fma2(unsigned long long a,
                                                   unsigned long long b,
                                                   unsigned long long c) {
    unsigned long long d;
    asm("fma.rn.f32x2 %0, %1, %2, %3;" : "=l"(d) : "l"(a), "l"(b), "l"(c));
    return d;
}
__device__ __forceinline__ unsigned long long pack2(float lo, float hi) {
    unsigned long long p;
    asm("mov.b64 %0, {%1, %2};" : "=l"(p) : "f"(lo), "f"(hi));
    return p;
}
__device__ __forceinline__ uint32_t smem_u32(const void* p) {
    uint32_t a;
    asm("{ .reg .u64 t; cvta.to.shared.u64 t, %1; cvt.u32.u64 %0, t; }" : "=r"(a) : "l"(p));
    return a;
}

// ---------------- Kernel 1 (merged launch): blocks <2500 do k1a, rest k1b ----------------
__global__ void k1_kernel(const float* __restrict__ x,
                          const float* __restrict__ na,
                          const float* __restrict__ W1_0,
                          const float* __restrict__ W1_1,
                          const float* __restrict__ W1_2,
                          const float* __restrict__ scW)
{
    extern __shared__ __align__(16) float dsm[];
    int t = threadIdx.x;

    if (blockIdx.x < 2500) {
        // ------- k1a: y0/y1/y2 pre-linear + zero mid -------
        float* w0s = dsm;
        float* w1s = dsm + 1024;
        float* w2s = dsm + 2048;
        for (int i = t; i < 1024; i += blockDim.x) {
            w0s[i] = W1_0[i]; w1s[i] = W1_1[i]; w2s[i] = W1_2[i];
        }
        __syncthreads();

        int lane = t & 31;
        int n = (int)((blockIdx.x * blockDim.x + t) >> 5);
        if (n >= N_NODES) return;

        const float* xr = x + (size_t)n * 288;
        float x0r = xr[lane];
        float x1r[3], x2r[5];
#pragma unroll
        for (int m = 0; m < 3; m++) x1r[m] = xr[32 + lane * 3 + m];
#pragma unroll
        for (int m = 0; m < 5; m++) x2r[m] = xr[128 + lane * 5 + m];

        float a0 = 0.f;
        float a1[3] = {0.f, 0.f, 0.f};
        float a2[5] = {0.f, 0.f, 0.f, 0.f, 0.f};
#pragma unroll
        for (int u = 0; u < 32; u++) {
            float xv0 = __shfl_sync(0xffffffffu, x0r, u);
            a0 = fmaf(xv0, w0s[u * 32 + lane], a0);
#pragma unroll
            for (int m = 0; m < 3; m++) {
                float xv = __shfl_sync(0xffffffffu, x1r[m], u);
                a1[m] = fmaf(xv, w1s[u * 32 + lane], a1[m]);
            }
#pragma unroll
            for (int m = 0; m < 5; m++) {
                float xv = __shfl_sync(0xffffffffu, x2r[m], u);
                a2[m] = fmaf(xv, w2s[u * 32 + lane], a2[m]);
            }
        }
        const float inv = 0.17677669529663687f; // 1/sqrt(32)
        g_y0[n * 32 + lane] = a0 * inv;
#pragma unroll
        for (int m = 0; m < 3; m++) g_y1t[(n * 3 + m) * 32 + lane] = a1[m] * inv;
#pragma unroll
        for (int m = 0; m < 5; m++) g_y2t[(n * 5 + m) * 32 + lane] = a2[m] * inv;

        g_mid[n * 96 + lane]      = 0.f;
        g_mid[n * 96 + 32 + lane] = 0.f;
        g_mid[n * 96 + 64 + lane] = 0.f;
    } else {
        // ------- k1b: self-connection sc -------
        float* s = dsm; // 12288 floats
        for (int i = t; i < 12288; i += blockDim.x) s[i] = scW[i];
        __syncthreads();

        int lane = t & 31;
        int n = (int)(((blockIdx.x - 2500) * blockDim.x + t) >> 5);
        if (n >= N_NODES) return;

        float x0r = x[(size_t)n * 288 + lane];
        float nar = (lane < 4) ? na[n * 4 + lane] : 0.f;
        float na0 = __shfl_sync(0xffffffffu, nar, 0);
        float na1 = __shfl_sync(0xffffffffu, nar, 1);
        float na2 = __shfl_sync(0xffffffffu, nar, 2);
        float na3 = __shfl_sync(0xffffffffu, nar, 3);

        float acc[3] = {0.f, 0.f, 0.f};
#pragma unroll
        for (int u = 0; u < 32; u++) {
            float x0u = __shfl_sync(0xffffffffu, x0r, u);
            float c0 = x0u * na0, c1 = x0u * na1, c2 = x0u * na2, c3 = x0u * na3;
#pragma unroll
            for (int h = 0; h < 3; h++) {
                const float* p = s + ((h * 32 + u) * 4) * 32 + lane;
                acc[h] = fmaf(c0, p[0],  acc[h]);
                acc[h] = fmaf(c1, p[32], acc[h]);
                acc[h] = fmaf(c2, p[64], acc[h]);
                acc[h] = fmaf(c3, p[96], acc[h]);
            }
        }
        const float invs = 0.08838834764831845f; // 1/sqrt(128)
#pragma unroll
        for (int h = 0; h < 3; h++)
            g_sc[h * (N_NODES * 32) + n * 32 + lane] = acc[h] * invs;
    }
}

// ---------------- Kernel 2: HMMA bf16-split edge pipeline, gather hoisted ----------------
// 128 threads = 4 independent warps; each warp owns 16 edges per iteration.
// smem: wm0s f32[512] | W bf16[96][136] | H bf16[4][16][136] | zbuf f32[4][16][100] | ea f32[4][144]
__global__ void __launch_bounds__(128, 3) k2_kernel(const float* __restrict__ ee,
                          const float* __restrict__ ea,
                          const int*   __restrict__ eidx,
                          const float* __restrict__ Wm0,
                          const float* __restrict__ Wm1)
{
    extern __shared__ __align__(16) unsigned char smraw[];
    float*          wm0s = (float*)smraw;                          // [0, 2048)
    __nv_bfloat16*  Wb   = (__nv_bfloat16*)(smraw + 2048);         // [2048, 28160)
    float*          zbuf = (float*)(smraw + 45568);                // [45568, 71168)
    float*          ea_s = (float*)(smraw + 71168);                // [71168, 73472)

    const uint32_t sb    = smem_u32(smraw);
    const uint32_t W_u32 = sb + 2048;
    const uint32_t H_u32 = sb + 28160;

    int tid  = threadIdx.x;
    int lane = tid & 31;
    int wrp  = tid >> 5;

    const float inv8 = 0.35355339059327373f;          // 1/sqrt(8)
    const float C0 = 0.125f * 0.17677669529663687f;   // invh*savg
    const float C1 = C0 * 0.5773502691896258f;        // *1/sqrt3
    const float C2 = C0 * 0.4472135954999579f;        // *1/sqrt5

    // one-time: scaled Wm0
    for (int i = tid; i < 512; i += 128) wm0s[i] = Wm0[i] * inv8;
    // one-time: split-bf16 of Wm1 with column scales folded
    for (int i = tid; i < 96 * 64; i += 128) {
        int n = i >> 6, k = i & 63;
        float Cn = (n < 32) ? C0 : (n < 64) ? C1 : C2;
        float w = Wm1[k * 96 + n] * Cn;
        __nv_bfloat16 hb = __float2bfloat16(w);
        Wb[n * 136 + k]      = hb;
        Wb[n * 136 + 64 + k] = __float2bfloat16(w - __bfloat162float(hb));
    }
    __syncthreads();

    float* ea_w = ea_s + wrp * 144;
    float* zb   = zbuf + wrp * 1600;
    const uint32_t Hw = H_u32 + wrp * 4352;

    int eloc = lane >> 1, half = lane & 1;
    const float* wp = wm0s + (half << 5);

    const uint32_t a_base = Hw + (uint32_t)(lane & 15) * 272 + (uint32_t)((lane >> 4) & 1) * 16;
    const uint32_t b_base = W_u32 + (uint32_t)(lane & 7) * 272 + (uint32_t)((lane >> 3) & 1) * 16;
    const uint32_t hrow = Hw + (uint32_t)eloc * 272 + (uint32_t)half * 64;

    int wg = blockIdx.x * 4 + wrp;
    int nw = gridDim.x * 4;

    for (int g = wg; g < N_EDGES / 16; g += nw) {
        int base = g * 16;

        // ---- stage edge attrs ----
        for (int i = lane; i < 144; i += 32)
            ea_w[i] = __ldg(ea + (size_t)base * 9 + i);

        // ---- first MLP: 2 lanes per edge ----
        float ev[8];
        {
            const float4* p = (const float4*)(ee + (size_t)(base + eloc) * 8);
            float4 va = __ldg(p), vb = __ldg(p + 1);
            ev[0]=va.x; ev[1]=va.y; ev[2]=va.z; ev[3]=va.w;
            ev[4]=vb.x; ev[5]=vb.y; ev[6]=vb.z; ev[7]=vb.w;
        }
        unsigned long long hacc[16];
#pragma unroll
        for (int j = 0; j < 16; j++) hacc[j] = 0ull;
#pragma unroll
        for (int k = 0; k < 8; k++) {
            unsigned long long ek2 = pack2(ev[k], ev[k]);
            const ulonglong2* q = (const ulonglong2*)(wp + (k << 6));
#pragma unroll
            for (int j = 0; j < 8; j++) {
                ulonglong2 v = q[j];
                hacc[2 * j]     = fma2(ek2, v.x, hacc[2 * j]);
                hacc[2 * j + 1] = fma2(ek2, v.y, hacc[2 * j + 1]);
            }
        }
#pragma unroll
        for (int j = 0; j < 16; j++) {
            float s0, s1;
            asm("mov.b64 {%0,%1}, %2;" : "=f"(s0), "=f"(s1) : "l"(hacc[j]));
            s0 = silu_f(s0); s1 = silu_f(s1);
            uint32_t hb;
            asm("cvt.rn.bf16x2.f32 %0, %1, %2;" : "=r"(hb) : "f"(s1), "f"(s0));
            float f0 = __uint_as_float(hb << 16);
            float f1 = __uint_as_float(hb & 0xFFFF0000u);
            float r0 = s0 - f0, r1 = s1 - f1;
            uint32_t lb;
            asm("cvt.rn.bf16x2.f32 %0, %1, %2;" : "=r"(lb) : "f"(r1), "f"(r0));
            asm volatile("st.shared.b32 [%0], %1;" :: "r"(hrow + j * 4), "r"(hb) : "memory");
            asm volatile("st.shared.b32 [%0], %1;" :: "r"(hrow + 128 + j * 4), "r"(lb) : "memory");
        }
        __syncwarp();

        // ---- hoisted gather contraction -> zbuf (independent of GEMM) ----
#pragma unroll
        for (int le = 0; le < 16; le++) {
            int s = __ldg(eidx + base + le);
            const float* eap = ea_w + le * 9;
            float y0v = __ldg(g_y0 + (size_t)s * 32 + lane);
            float z1 = __ldg(g_y1t + (size_t)s * 96 + lane) * eap[1];
            z1 = fmaf(__ldg(g_y1t + (size_t)s * 96 + 32 + lane), eap[2], z1);
            z1 = fmaf(__ldg(g_y1t + (size_t)s * 96 + 64 + lane), eap[3], z1);
            float z2 = __ldg(g_y2t + (size_t)s * 160 + lane) * eap[4];
            z2 = fmaf(__ldg(g_y2t + (size_t)s * 160 + 32 + lane),  eap[5], z2);
            z2 = fmaf(__ldg(g_y2t + (size_t)s * 160 + 64 + lane),  eap[6], z2);
            z2 = fmaf(__ldg(g_y2t + (size_t)s * 160 + 96 + lane),  eap[7], z2);
            z2 = fmaf(__ldg(g_y2t + (size_t)s * 160 + 128 + lane), eap[8], z2);

            zb[le * 100 + lane]      = y0v * eap[0];
            zb[le * 100 + 32 + lane] = z1;
            zb[le * 100 + 64 + lane] = z2;
        }
        __syncwarp();

        // ---- GEMM: D[16,96] = Hhi*Whi + Hlo*Whi + Hhi*Wlo ----
        float acc[48];
#pragma unroll
        for (int i = 0; i < 48; i++) acc[i] = 0.f;
#pragma unroll
        for (int k = 0; k < 4; k++) {
            uint32_t ah0, ah1, ah2, ah3, al0, al1, al2, al3;
            asm volatile("ldmatrix.sync.aligned.m8n8.x4.shared.b16 {%0,%1,%2,%3}, [%4];"
                         : "=r"(ah0), "=r"(ah1), "=r"(ah2), "=r"(ah3)
                         : "r"(a_base + k * 32));
            asm volatile("ldmatrix.sync.aligned.m8n8.x4.shared.b16 {%0,%1,%2,%3}, [%4];"
                         : "=r"(al0), "=r"(al1), "=r"(al2), "=r"(al3)
                         : "r"(a_base + 128 + k * 32));
#pragma unroll
            for (int n = 0; n < 12; n++) {
                uint32_t baddr = b_base + (uint32_t)n * 2176 + k * 32;
                uint32_t bh0, bh1, bl0, bl1;
                asm volatile("ldmatrix.sync.aligned.m8n8.x2.shared.b16 {%0,%1}, [%2];"
                             : "=r"(bh0), "=r"(bh1) : "r"(baddr));
                asm volatile("ldmatrix.sync.aligned.m8n8.x2.shared.b16 {%0,%1}, [%2];"
                             : "=r"(bl0), "=r"(bl1) : "r"(baddr + 128));
                float* d = acc + n * 4;
                asm volatile("mma.sync.aligned.m16n8k16.row.col.f32.bf16.bf16.f32 "
                             "{%0,%1,%2,%3}, {%4,%5,%6,%7}, {%8,%9}, {%0,%1,%2,%3};"
                             : "+f"(d[0]), "+f"(d[1]), "+f"(d[2]), "+f"(d[3])
                             : "r"(ah0), "r"(ah1), "r"(ah2), "r"(ah3), "r"(bh0), "r"(bh1));
                asm volatile("mma.sync.aligned.m16n8k16.row.col.f32.bf16.bf16.f32 "
                             "{%0,%1,%2,%3}, {%4,%5,%6,%7}, {%8,%9}, {%0,%1,%2,%3};"
                             : "+f"(d[0]), "+f"(d[1]), "+f"(d[2]), "+f"(d[3])
                             : "r"(al0), "r"(al1), "r"(al2), "r"(al3), "r"(bh0), "r"(bh1));
                asm volatile("mma.sync.aligned.m16n8k16.row.col.f32.bf16.bf16.f32 "
                             "{%0,%1,%2,%3}, {%4,%5,%6,%7}, {%8,%9}, {%0,%1,%2,%3};"
                             : "+f"(d[0]), "+f"(d[1]), "+f"(d[2]), "+f"(d[3])
                             : "r"(ah0), "r"(ah1), "r"(ah2), "r"(ah3), "r"(bl0), "r"(bl1));
            }
        }

        // ---- fused epilogue: multiply D fragment by zbuf in place ----
        {
            int q = lane >> 2, tg = lane & 3;
#pragma unroll
            for (int n = 0; n < 12; n++) {
                int col = n * 8 + tg * 2;
                float2 za = *(float2*)&zb[q * 100 + col];
                float2 zc = *(float2*)&zb[(q + 8) * 100 + col];
                za.x *= acc[n * 4];     za.y *= acc[n * 4 + 1];
                zc.x *= acc[n * 4 + 2]; zc.y *= acc[n * 4 + 3];
                *(float2*)&zb[q * 100 + col]       = za;
                *(float2*)&zb[(q + 8) * 100 + col] = zc;
            }
        }
        __syncwarp();

        // ---- vector atomic scatter ----
        if (lane < 24) {
#pragma unroll 4
            for (int le = 0; le < 16; le++) {
                int d = __ldg(eidx + N_EDGES + base + le);
                float4 v = *(const float4*)&zb[le * 100 + lane * 4];
                float* p = &g_mid[(size_t)d * 96 + lane * 4];
                asm volatile("red.global.add.v4.f32 [%0], {%1,%2,%3,%4};"
                             :: "l"(p), "f"(v.x), "f"(v.y), "f"(v.z), "f"(v.w)
                             : "memory");
            }
        }
        __syncwarp();
    }
}

// ---------------- Kernel 3: node finalize (transposed weights + f32x2) ----------------
__global__ void k3_kernel(const float* __restrict__ l2_0,
                          const float* __restrict__ l2_1,
                          const float* __restrict__ l2_2,
                          float* __restrict__ out)
{
    __shared__ __align__(16) float s0t[32 * 36];
    __shared__ __align__(16) float s1t[32 * 68];
    __shared__ __align__(16) float s2t[32 * 100];
    __shared__ __align__(16) float mb[8][96];

    int t = threadIdx.x;
    for (int i = t; i < 1024; i += blockDim.x) { int k = i / 32, w = i % 32; s0t[w * 36 + k]  = l2_0[i]; }
    for (int i = t; i < 2048; i += blockDim.x) { int k = i / 32, w = i % 32; s1t[w * 68 + k]  = l2_1[i]; }
    for (int i = t; i < 3072; i += blockDim.x) { int k = i / 32, w = i % 32; s2t[w * 100 + k] = l2_2[i]; }
    __syncthreads();

    int lane = t & 31;
    int wrp  = t >> 5;
    int n = (int)((blockIdx.x * blockDim.x + t) >> 5);
    if (n >= N_NODES) return;

    mb[wrp][lane]      = g_mid[n * 96 + lane];
    mb[wrp][32 + lane] = g_mid[n * 96 + 32 + lane];
    mb[wrp][64 + lane] = g_mid[n * 96 + 64 + lane];
    __syncwarp();

    unsigned long long A0 = 0ull, A1 = 0ull, A2 = 0ull, B2 = 0ull;
    const float* p0 = &s0t[lane * 36];
    const float* p1 = &s1t[lane * 68];
    const float* p2 = &s2t[lane * 100];
#pragma unroll
    for (int c = 0; c < 24; c++) {
        int k = c * 4;
        ulonglong2 m4 = *(const ulonglong2*)&mb[wrp][k];
        ulonglong2 q2 = *(const ulonglong2*)(p2 + k);
        A2 = fma2(m4.x, q2.x, A2);
        B2 = fma2(m4.y, q2.y, B2);
        if (c < 16) {
            ulonglong2 q1 = *(const ulonglong2*)(p1 + k);
            A1 = fma2(m4.x, q1.x, A1);
            A1 = fma2(m4.y, q1.y, A1);
        }
        if (c < 8) {
            ulonglong2 q0 = *(const ulonglong2*)(p0 + k);
            A0 = fma2(m4.x, q0.x, A0);
            A0 = fma2(m4.y, q0.y, A0);
        }
    }

    const float i32 = 0.17677669529663687f;
    const float i64 = 0.125f;
    const float i96 = 0.10206207261596575f;

    float a0lo, a0hi, a1lo, a1hi, a2lo, a2hi, b2lo, b2hi;
    asm("mov.b64 {%0,%1}, %2;" : "=f"(a0lo), "=f"(a0hi) : "l"(A0));
    asm("mov.b64 {%0,%1}, %2;" : "=f"(a1lo), "=f"(a1hi) : "l"(A1));
    asm("mov.b64 {%0,%1}, %2;" : "=f"(a2lo), "=f"(a2hi) : "l"(A2));
    asm("mov.b64 {%0,%1}, %2;" : "=f"(b2lo), "=f"(b2hi) : "l"(B2));

    float o0 = silu_f(fmaf(a0lo + a0hi, i32, g_sc[                   n * 32 + lane]));
    float o1 = silu_f(fmaf(a1lo + a1hi, i64, g_sc[N_NODES * 32     + n * 32 + lane]));
    float o2 = silu_f(fmaf((a2lo + a2hi) + (b2lo + b2hi), i96, g_sc[2 * N_NODES * 32 + n * 32 + lane]));

    out[                   n * 32 + lane] = o0;
    out[N_NODES * 32     + n * 32 + lane] = o1;
    out[2 * N_NODES * 32  + n * 32 + lane] = o2;
}

// ---------------- launch ----------------
extern "C" void kernel_launch(void* const* d_in, const int* in_sizes, int n_in,
                              void* d_out, int out_size)
{
    const float* x      = (const float*)d_in[0];
    const float* na     = (const float*)d_in[1];
    const float* ee     = (const float*)d_in[2];
    const float* ea     = (const float*)d_in[3];
    const int*   eidx   = (const int*)  d_in[4];
    const float* W1_0   = (const float*)d_in[5];
    const float* W1_1   = (const float*)d_in[6];
    const float* W1_2   = (const float*)d_in[7];
    const float* Wm0    = (const float*)d_in[8];
    const float* Wm1    = (const float*)d_in[9];
    const float* l2_0   = (const float*)d_in[10];
    const float* l2_1   = (const float*)d_in[11];
    const float* l2_2   = (const float*)d_in[12];
    const float* scW    = (const float*)d_in[13];
    float* out = (float*)d_out;

    cudaFuncSetAttribute(k1_kernel, cudaFuncAttributeMaxDynamicSharedMemorySize, 49152);
    cudaFuncSetAttribute(k2_kernel, cudaFuncAttributeMaxDynamicSharedMemorySize, K2_SMEM);

    k1_kernel<<<5000, 256, 49152>>>(x, na, W1_0, W1_1, W1_2, scW);
    k2_kernel<<<K2_BLOCKS, 128, K2_SMEM>>>(ee, ea, eidx, Wm0, Wm1);
    k3_kernel<<<2500, 256>>>(l2_0, l2_1, l2_2, out);
    (void)in_sizes; (void)n_in; (void)out_size;
}